// round 8
// baseline (speedup 1.0000x reference)
#include <cuda_runtime.h>
#include <cuda_fp16.h>
#include <cstdint>

#define B_NODES 8192
#define ZS      10
#define INC     512
#define OUTC    512
#define MD      3
#define ALPHA   0.04419417382415922f   // 1/sqrt(512)

#define NT      64                     // nodes per tile
#define NCOLS   (NT*MD)                // 192
#define CT      128                    // C tile
#define KT      32                     // k (halves) per stage
#define KSTAGES (INC/KT)               // 16
#define NSTAGES 6                      // smem ring depth
#define NTHREADS 512
#define TILES   138

#define A_BYTES    (CT*KT*2)           // 8192
#define B_BYTES    (NCOLS*KT*2)       // 12288
#define STAGE_BYTES (A_BYTES+B_BYTES)  // 20480
#define GEMM_SMEM  (NSTAGES*STAGE_BYTES) // 122880
#define OSTR 388                       // epilogue smem row stride (floats)

#define WBLKS 160                      // W-convert blocks in fused k_bhwh (x dim)

// --------- scratch ----------
__device__ int g_tilez[TILES];
__device__ int g_psorted[TILES * NT];
__device__ __half Wh[(size_t)ZS * OUTC * INC];       // [z][c][k] fp16
__device__ __half Bh[(size_t)TILES * NCOLS * INC];   // [tile][n][k] fp16

// --------- helpers ----------
__device__ __forceinline__ void cpa16(void* dst, const void* src) {
    uint32_t d = (uint32_t)__cvta_generic_to_shared(dst);
    asm volatile("cp.async.cg.shared.global [%0], [%1], 16;" :: "r"(d), "l"(src) : "memory");
}
#define LDSM_X4(r, a) \
    asm volatile("ldmatrix.sync.aligned.m8n8.x4.shared.b16 {%0,%1,%2,%3}, [%4];" \
        : "=r"((r)[0]), "=r"((r)[1]), "=r"((r)[2]), "=r"((r)[3]) : "r"(a))

__device__ __forceinline__ void mma_f16(float* c, const uint32_t* a, const uint32_t* b) {
    asm volatile(
        "mma.sync.aligned.m16n8k16.row.col.f32.f16.f16.f32 "
        "{%0,%1,%2,%3}, {%4,%5,%6,%7}, {%8,%9}, {%0,%1,%2,%3};"
        : "+f"(c[0]), "+f"(c[1]), "+f"(c[2]), "+f"(c[3])
        : "r"(a[0]), "r"(a[1]), "r"(a[2]), "r"(a[3]), "r"(b[0]), "r"(b[1]));
}

// --------- fused prep: classify + histogram + scan + fill + scatter ----------
// one block, 1024 threads
__global__ __launch_bounds__(1024)
void k_prep(const float* __restrict__ attrs)
{
    __shared__ int hist[ZS];
    __shared__ int cursor[ZS];
    const int tid = threadIdx.x;

    if (tid < ZS) hist[tid] = 0;
    __syncthreads();

    int myspec[8];
#pragma unroll
    for (int j = 0; j < 8; j++) {
        int b = j * 1024 + tid;
        int s = 0;
#pragma unroll
        for (int z = 0; z < ZS; z++)
            s = (attrs[b * ZS + z] > 0.5f) ? z : s;
        myspec[j] = s;
        atomicAdd(&hist[s], 1);
    }
    __syncthreads();

    if (tid == 0) {
        int acc = 0;
        for (int z = 0; z < ZS; z++) {
            cursor[z] = acc;
            int tiles = (hist[z] + NT - 1) / NT;
            for (int ti = 0; ti < tiles; ti++) g_tilez[acc / NT + ti] = z;
            acc += tiles * NT;
        }
        for (int ti = acc / NT; ti < TILES; ti++) g_tilez[ti] = -1;
    }
    // fill sentinel everywhere (scatter overwrites live slots)
    for (int i = tid; i < TILES * NT; i += 1024) g_psorted[i] = -1;
    __syncthreads();

#pragma unroll
    for (int j = 0; j < 8; j++) {
        int b = j * 1024 + tid;
        int s = myspec[j];
        int pos = atomicAdd(&cursor[s], 1);
        g_psorted[pos] = b;
    }
}

// --------- fused: Bh gather/convert/transpose  +  Wh convert ----------
#define SHB 196
__global__ void k_bhwh(const float* __restrict__ t, const float* __restrict__ W) {
    int bx = blockIdx.x;
    int tid = threadIdx.x;

    if (bx >= TILES) {
        // ---- W -> fp16 chunk ----
        int c = (bx - TILES) * 8 + blockIdx.y;           // 0..1279
        size_t i = ((size_t)c * 256 + tid) * 8;
        float4 v0 = *(const float4*)(W + i);
        float4 v1 = *(const float4*)(W + i + 4);
        __half2 h[4];
        h[0] = __floats2half2_rn(v0.x, v0.y);
        h[1] = __floats2half2_rn(v0.z, v0.w);
        h[2] = __floats2half2_rn(v1.x, v1.y);
        h[3] = __floats2half2_rn(v1.z, v1.w);
        *(uint4*)(Wh + i) = *(uint4*)h;
        return;
    }

    int tile = bx;
    if (g_tilez[tile] < 0) return;
    int kc = blockIdx.y;                     // 64-k chunk (8 per tile)
    extern __shared__ float sh[];            // [64 nodes][196]
#pragma unroll
    for (int i = 0; i < 12; i++) {
        int idx = i * 256 + tid;             // 3072 float4s
        int nl = idx / 48, f4 = idx % 48;
        int node = g_psorted[tile * NT + nl];
        float4 v = make_float4(0.f, 0.f, 0.f, 0.f);
        if (node >= 0)
            v = *(const float4*)(t + (size_t)node * (INC * MD) + kc * 192 + f4 * 4);
        int base = nl * SHB + f4 * 4;
        sh[base + 0] = v.x; sh[base + 1] = v.y;
        sh[base + 2] = v.z; sh[base + 3] = v.w;
    }
    __syncthreads();
    __half* dst = Bh + (size_t)tile * NCOLS * INC + kc * 64;
#pragma unroll
    for (int i = 0; i < 12; i++) {
        int idx = i * 256 + tid;             // 192 n-rows x 16 quad-groups
        int n = idx / 16, kq = idx % 16;
        int nl = n / 3, d = n % 3;
        float x = sh[nl * SHB + (kq * 4 + 0) * 3 + d];
        float y = sh[nl * SHB + (kq * 4 + 1) * 3 + d];
        float zv = sh[nl * SHB + (kq * 4 + 2) * 3 + d];
        float w = sh[nl * SHB + (kq * 4 + 3) * 3 + d];
        __half2 p[2];
        p[0] = __floats2half2_rn(x, y);
        p[1] = __floats2half2_rn(zv, w);
        *(uint2*)(dst + (size_t)n * INC + kq * 4) = *(uint2*)p;
    }
}

// --------- GEMM: cp.async 6-stage ring + ldmatrix + fp16 mma ----------
__global__ __launch_bounds__(NTHREADS, 1)
void k_gemm(float* __restrict__ out)
{
    const int tile = blockIdx.x;
    const int z = g_tilez[tile];
    if (z < 0) return;
    const int c0 = blockIdx.y * CT;

    extern __shared__ float sm[];
    char* smc = (char*)sm;
    __shared__ int nodes_s[NT];

    const int tid = threadIdx.x;
    if (tid < NT) nodes_s[tid] = g_psorted[tile * NT + tid];

    const int lane = tid & 31;
    const int wid  = tid >> 5;
    const int wm   = wid & 3;
    const int wn   = wid >> 2;
    const int g    = lane >> 2;
    const int tg   = lane & 3;

    const __half* abase = Wh + ((size_t)z * OUTC + c0) * INC;
    const __half* bbase = Bh + (size_t)tile * NCOLS * INC;

    // A: 512 16B-chunks/stage (128 rows x 4), B: 768 (192 rows x 4)
    auto issue = [&](int s) {
        char* ab = smc + (s % NSTAGES) * STAGE_BYTES;
        const __half* asrc = abase + s * KT;
        {
            int m = tid >> 2, c = tid & 3;
            cpa16(ab + m * 64 + ((c ^ ((m >> 1) & 3)) << 4),
                  asrc + (size_t)m * INC + c * 8);
        }
        char* bb = ab + A_BYTES;
        const __half* bsrc = bbase + s * KT;
#pragma unroll
        for (int i = 0; i < 2; i++) {
            int idx = i * NTHREADS + tid;
            if (idx < 768) {
                int n = idx >> 2, c = idx & 3;
                cpa16(bb + n * 64 + ((c ^ ((n >> 1) & 3)) << 4),
                      bsrc + (size_t)n * INC + c * 8);
            }
        }
    };

#pragma unroll
    for (int p = 0; p < NSTAGES - 1; p++) {
        issue(p);
        asm volatile("cp.async.commit_group;" ::: "memory");
    }

    // ---- per-lane ldmatrix addressing ----
    const int mi = lane >> 3;              // matrix index 0..3 within x4
    const int mr = lane & 7;
    uint32_t aoff[2], a3[2];
#pragma unroll
    for (int mt = 0; mt < 2; mt++) {
        int m = wm * 32 + mt * 16 + (mi & 1) * 8 + mr;
        aoff[mt] = (uint32_t)m * 64;
        a3[mt] = (uint32_t)((m >> 1) & 3);
    }
    const uint32_t akc = (uint32_t)(mi >> 1);
    uint32_t boff[3], b3[3];
#pragma unroll
    for (int p = 0; p < 3; p++) {
        int n = wn * 48 + p * 16 + (mi >> 1) * 8 + mr;
        boff[p] = (uint32_t)n * 64;
        b3[p] = (uint32_t)((n >> 1) & 3);
    }
    const uint32_t bkc = (uint32_t)(mi & 1);
    const uint32_t smbase = (uint32_t)__cvta_generic_to_shared(sm);

    float acc[2][6][4];
#pragma unroll
    for (int i = 0; i < 2; i++)
#pragma unroll
        for (int j = 0; j < 6; j++)
#pragma unroll
            for (int e = 0; e < 4; e++) acc[i][j][e] = 0.f;

    for (int s = 0; s < KSTAGES; s++) {
        asm volatile("cp.async.wait_group %0;" :: "n"(NSTAGES - 2) : "memory");
        __syncthreads();
        if (s + NSTAGES - 1 < KSTAGES) issue(s + NSTAGES - 1);
        asm volatile("cp.async.commit_group;" ::: "memory");

        const uint32_t sA = smbase + (s % NSTAGES) * STAGE_BYTES;
        const uint32_t sB = sA + A_BYTES;
#pragma unroll
        for (int kc = 0; kc < 2; kc++) {
            uint32_t a[2][4];
#pragma unroll
            for (int mt = 0; mt < 2; mt++)
                LDSM_X4(a[mt], sA + aoff[mt] + (((((uint32_t)kc << 1) + akc) ^ a3[mt]) << 4));
            uint32_t b[3][4];
#pragma unroll
            for (int p = 0; p < 3; p++)
                LDSM_X4(b[p], sB + boff[p] + (((((uint32_t)kc << 1) + bkc) ^ b3[p]) << 4));
#pragma unroll
            for (int mt = 0; mt < 2; mt++)
#pragma unroll
                for (int nt = 0; nt < 6; nt++)
                    mma_f16(acc[mt][nt], a[mt], b[nt >> 1] + (nt & 1) * 2);
        }
    }

    // ---- epilogue: acc -> smem [node][C*3+d] -> coalesced out ----
    __syncthreads();
#pragma unroll
    for (int mt = 0; mt < 2; mt++) {
#pragma unroll
        for (int nt = 0; nt < 6; nt++) {
#pragma unroll
            for (int e = 0; e < 4; e++) {
                int Cl = wm * 32 + mt * 16 + g + (e >> 1) * 8;
                int j  = wn * 48 + nt * 8 + 2 * tg + (e & 1);
                int nl = j / 3, d = j - nl * 3;
                sm[nl * OSTR + Cl * 3 + d] = acc[mt][nt][e] * ALPHA;
            }
        }
    }
    __syncthreads();
#pragma unroll
    for (int i = 0; i < 12; i++) {
        int idx = i * NTHREADS + tid;              // 6144 float4s
        int nl = idx / 96, f4 = idx % 96;
        int node = nodes_s[nl];
        if (node >= 0) {
            float4 v = *(const float4*)(sm + nl * OSTR + f4 * 4);
            *(float4*)(out + (size_t)node * (OUTC * MD) + c0 * 3 + f4 * 4) = v;
        }
    }
}

// --------- entry point ----------
extern "C" void kernel_launch(void* const* d_in, const int* in_sizes, int n_in,
                              void* d_out, int out_size)
{
    const float* t     = (const float*)d_in[0];   // [B, IN, M]
    const float* attrs = (const float*)d_in[1];   // [B, Z]
    const float* W     = (const float*)d_in[2];   // [Z, OUT, IN]
    float* out = (float*)d_out;                   // [B, OUT, M]

    k_prep<<<1, 1024>>>(attrs);

    cudaFuncSetAttribute(k_bhwh, cudaFuncAttributeMaxDynamicSharedMemorySize, NT * SHB * 4);
    k_bhwh<<<dim3(TILES + WBLKS, 8), 256, NT * SHB * 4>>>(t, W);

    cudaFuncSetAttribute(k_gemm, cudaFuncAttributeMaxDynamicSharedMemorySize, GEMM_SMEM);
    k_gemm<<<dim3(TILES, OUTC / CT), NTHREADS, GEMM_SMEM>>>(out);
}